// round 7
// baseline (speedup 1.0000x reference)
#include <cuda_runtime.h>
#include <cstdint>

#define S_LEN   2048
#define HID     4096
#define I_DIM   8192
#define CD      10240
#define H_HEADS 128
#define P_DIM   64
#define G_GRP   8
#define N_STATE 128
#define KCONV   4
#define PROJ    18560   // I + CD + H

// device scratch
__device__ float g_proj  [(size_t)S_LEN * PROJ ];
__device__ float g_conv  [(size_t)S_LEN * CD   ];
__device__ float g_y     [(size_t)S_LEN * I_DIM];
__device__ float g_normed[(size_t)S_LEN * I_DIM];

__device__ __forceinline__ uint32_t to_tf32_u(float x) {
    uint32_t u; asm("cvt.rna.tf32.f32 %0, %1;" : "=r"(u) : "f"(x));
    return u;
}
__device__ __forceinline__ void mma_tf32(float* d, const uint32_t* a, const uint32_t* b) {
    asm volatile("mma.sync.aligned.m16n8k8.row.col.f32.tf32.tf32.f32 "
        "{%0,%1,%2,%3}, {%4,%5,%6,%7}, {%8,%9}, {%0,%1,%2,%3};\n"
        : "+f"(d[0]), "+f"(d[1]), "+f"(d[2]), "+f"(d[3])
        : "r"(a[0]), "r"(a[1]), "r"(a[2]), "r"(a[3]), "r"(b[0]), "r"(b[1]));
}
__device__ __forceinline__ void cp_async16(void* smem_dst, const void* gmem_src) {
    uint32_t s = (uint32_t)__cvta_generic_to_shared(smem_dst);
    asm volatile("cp.async.cg.shared.global [%0], [%1], 16;" :: "r"(s), "l"(gmem_src) : "memory");
}
__device__ __forceinline__ float silu_f(float v) { return v / (1.0f + expf(-v)); }

// ---------------- GEMM (NT): C[M][Nn] = A[M][Kk] * B[Nn][Kk]^T ----------------
// Block tile 128x128x16, 8 warps (warp tile 64x32), 4-stage cp.async pipeline,
// 2 CTAs/SM. Grid: x = m-tile (fast) so co-resident CTAs share B n-tiles in L2.
// Requirements: M,Nn multiples of 128; Kk multiple of 16 (true for all calls).
#define GSTG  4
#define KT    16
#define RS    20            // smem row stride (floats): 80B, 16B-aligned, conflict-free frags
#define TILEF (128 * RS)

__global__ __launch_bounds__(256, 2)
void gemm_tf32_nt(const float* __restrict__ A, const float* __restrict__ B,
                  float* __restrict__ C, int M, int Nn, int Kk)
{
    extern __shared__ float sm_[];
    float* Asm = sm_;                  // [GSTG][TILEF]
    float* Bsm = sm_ + GSTG * TILEF;   // [GSTG][TILEF]

    const int tid = threadIdx.x, lane = tid & 31, wid = tid >> 5;
    const int gid = lane >> 2, tig = lane & 3;
    const int wm = (wid >> 2) * 64, wn = (wid & 3) * 32;
    const int m0 = blockIdx.x * 128, n0 = blockIdx.y * 128;   // m fast => B-tile reuse in L2
    const int lr = tid >> 2, lc4 = (tid & 3) << 2;

    float acc[4][4][4];
    #pragma unroll
    for (int i = 0; i < 4; i++)
        #pragma unroll
        for (int j = 0; j < 4; j++)
            #pragma unroll
            for (int r = 0; r < 4; r++) acc[i][j][r] = 0.f;

    const float* Abase = &A[(size_t)(m0 + lr) * Kk + lc4];
    const float* Bbase = &B[(size_t)(n0 + lr) * Kk + lc4];
    const size_t rsk = (size_t)64 * Kk;

    const int nk = Kk / KT;

    auto issue_stage = [&](int i) {
        if (i < nk) {
            const int k0 = i * KT, stg = i & (GSTG - 1);
            float* ad = Asm + stg * TILEF + lr * RS + lc4;
            float* bd = Bsm + stg * TILEF + lr * RS + lc4;
            cp_async16(ad,            Abase + k0);
            cp_async16(ad + 64 * RS,  Abase + k0 + rsk);
            cp_async16(bd,            Bbase + k0);
            cp_async16(bd + 64 * RS,  Bbase + k0 + rsk);
        }
        asm volatile("cp.async.commit_group;" ::: "memory");  // empty group past end keeps count uniform
    };

    issue_stage(0);
    issue_stage(1);
    issue_stage(2);

    for (int i = 0; i < nk; i++) {
        asm volatile("cp.async.wait_group 2;" ::: "memory");
        __syncthreads();
        // safe: buffer (i+3)&3 == (i-1)&3 was fully read before this barrier
        issue_stage(i + 3);

        const float* as = Asm + (i & (GSTG - 1)) * TILEF;
        const float* bs = Bsm + (i & (GSTG - 1)) * TILEF;

        #pragma unroll
        for (int ks = 0; ks < KT; ks += 8) {
            uint32_t af[4][4];
            #pragma unroll
            for (int mt = 0; mt < 4; mt++) {
                int r = wm + mt * 16 + gid;
                af[mt][0] = to_tf32_u(as[ r      * RS + ks + tig    ]);
                af[mt][1] = to_tf32_u(as[(r + 8) * RS + ks + tig    ]);
                af[mt][2] = to_tf32_u(as[ r      * RS + ks + tig + 4]);
                af[mt][3] = to_tf32_u(as[(r + 8) * RS + ks + tig + 4]);
            }
            uint32_t bf[4][2];
            #pragma unroll
            for (int nt = 0; nt < 4; nt++) {
                int cn = wn + nt * 8 + gid;
                bf[nt][0] = to_tf32_u(bs[cn * RS + ks + tig    ]);
                bf[nt][1] = to_tf32_u(bs[cn * RS + ks + tig + 4]);
            }
            #pragma unroll
            for (int mt = 0; mt < 4; mt++)
                #pragma unroll
                for (int nt = 0; nt < 4; nt++)
                    mma_tf32(acc[mt][nt], af[mt], bf[nt]);
        }
        // no trailing barrier: next iteration's barrier orders buffer reuse
    }

    #pragma unroll
    for (int mt = 0; mt < 4; mt++) {
        int row = m0 + wm + mt * 16 + gid;
        #pragma unroll
        for (int nt = 0; nt < 4; nt++) {
            int col = n0 + wn + nt * 8 + 2 * tig;
            *reinterpret_cast<float2*>(&C[(size_t)row       * Nn + col]) = make_float2(acc[mt][nt][0], acc[mt][nt][1]);
            *reinterpret_cast<float2*>(&C[(size_t)(row + 8) * Nn + col]) = make_float2(acc[mt][nt][2], acc[mt][nt][3]);
        }
    }
}
#define GEMM_SMEM (GSTG * TILEF * 2 * (int)sizeof(float))   // 81920 B

// ---------------- conv1d K=4 + SiLU ----------------
__global__ __launch_bounds__(256)
void conv_kernel(const float* __restrict__ proj, const float* __restrict__ cstate,
                 const float* __restrict__ cw, const float* __restrict__ cb,
                 float* __restrict__ convout)
{
    const int c  = blockIdx.x * 256 + threadIdx.x;
    const int s0 = blockIdx.y * 128;
    const float w0 = cw[c*4+0], w1 = cw[c*4+1], w2 = cw[c*4+2], w3 = cw[c*4+3];
    const float bb = cb[c];
    auto xr = [&](int r) -> float {
        return (r < 0) ? cstate[c*4 + r + 4] : proj[(size_t)r*PROJ + I_DIM + c];
    };
    float x0 = xr(s0-3), x1 = xr(s0-2), x2 = xr(s0-1);
    #pragma unroll 4
    for (int s = s0; s < s0 + 128; s++) {
        float x3 = xr(s);
        float a  = bb + x0*w0 + x1*w1 + x2*w2 + x3*w3;
        convout[(size_t)s*CD + c] = silu_f(a);
        x0 = x1; x1 = x2; x2 = x3;
    }
}

__global__ void cstate_out_kernel(const float* __restrict__ proj, float* __restrict__ outc)
{
    int i = blockIdx.x * 256 + threadIdx.x;
    if (i < CD * KCONV) {
        int c = i >> 2, k = i & 3;
        outc[i] = proj[(size_t)(S_LEN - KCONV + k)*PROJ + I_DIM + c];
    }
}

// ---------------- sequential SSM scan: 1 block/head ----------------
__global__ __launch_bounds__(256, 1)
void scan_kernel(const float* __restrict__ proj, const float* __restrict__ conv,
                 const float* __restrict__ state_in,
                 const float* __restrict__ A_log, const float* __restrict__ Dv,
                 const float* __restrict__ dt_bias,
                 float* __restrict__ y_out, float* __restrict__ state_out)
{
    const int h = blockIdx.x, tid = threadIdx.x;
    const int p = tid >> 2, q = tid & 3;
    const int g = h >> 4;

    __shared__ __align__(16) float xs [3][64];
    __shared__ __align__(16) float Bsh[3][4*36];
    __shared__ __align__(16) float Csh[3][4*36];
    __shared__ float dts[3];

    const float Ah  = -expf(A_log[h]);
    const float Dh  = Dv[h];
    const float dtb = dt_bias[h];

    float st[32];
    { const float4* sp = reinterpret_cast<const float4*>(&state_in[((size_t)(h*64+p))*128 + q*32]);
      #pragma unroll
      for (int j = 0; j < 8; j++) {
          float4 v = sp[j];
          st[4*j+0]=v.x; st[4*j+1]=v.y; st[4*j+2]=v.z; st[4*j+3]=v.w;
      } }

    float rx = 0.f, rdt = 0.f;
    float4 rB = make_float4(0,0,0,0), rC = rB;

    auto issue_load = [&](int s) {
        const float* row = conv + (size_t)s * CD;
        if (tid < 64)        rx = row[h*64 + tid];
        else if (tid < 96)   rB = reinterpret_cast<const float4*>(row + I_DIM + g*128)[tid-64];
        else if (tid < 128)  rC = reinterpret_cast<const float4*>(row + I_DIM + G_GRP*N_STATE + g*128)[tid-96];
        else if (tid == 128) rdt = proj[(size_t)s*PROJ + I_DIM + CD + h];
    };
    auto store_smem = [&](int buf) {
        if (tid < 64)        xs[buf][tid] = rx;
        else if (tid < 96)  { int j = tid-64, qq = j>>3, jj = j&7;
                              *reinterpret_cast<float4*>(&Bsh[buf][qq*36 + jj*4]) = rB; }
        else if (tid < 128) { int j = tid-96, qq = j>>3, jj = j&7;
                              *reinterpret_cast<float4*>(&Csh[buf][qq*36 + jj*4]) = rC; }
        else if (tid == 128) dts[buf] = rdt;
    };

    issue_load(0);
    for (int s = 0; s < S_LEN; s++) {
        const int buf = s % 3;
        store_smem(buf);
        __syncthreads();
        if (s + 1 < S_LEN) issue_load(s + 1);

        const float dtr = dts[buf] + dtb;
        const float dt  = (dtr > 20.f) ? dtr : log1pf(expf(dtr));
        const float dA  = expf(dt * Ah);
        const float xv  = xs[buf][p];
        const float dx  = dt * xv;

        float accv = 0.f;
        const float4* bp = reinterpret_cast<const float4*>(&Bsh[buf][q*36]);
        const float4* cp = reinterpret_cast<const float4*>(&Csh[buf][q*36]);
        #pragma unroll
        for (int jj = 0; jj < 8; jj++) {
            float4 b4 = bp[jj], c4 = cp[jj];
            st[4*jj+0] = st[4*jj+0]*dA + dx*b4.x; accv += st[4*jj+0]*c4.x;
            st[4*jj+1] = st[4*jj+1]*dA + dx*b4.y; accv += st[4*jj+1]*c4.y;
            st[4*jj+2] = st[4*jj+2]*dA + dx*b4.z; accv += st[4*jj+2]*c4.z;
            st[4*jj+3] = st[4*jj+3]*dA + dx*b4.w; accv += st[4*jj+3]*c4.w;
        }
        accv += __shfl_xor_sync(0xffffffffu, accv, 1);
        accv += __shfl_xor_sync(0xffffffffu, accv, 2);
        if (q == 0) y_out[(size_t)s*I_DIM + h*64 + p] = accv + Dh*xv;
    }

    { float4* spo = reinterpret_cast<float4*>(&state_out[((size_t)(h*64+p))*128 + q*32]);
      #pragma unroll
      for (int j = 0; j < 8; j++)
          spo[j] = make_float4(st[4*j], st[4*j+1], st[4*j+2], st[4*j+3]); }
}

// ---------------- gate * silu + grouped RMSNorm ----------------
__global__ __launch_bounds__(256)
void gatenorm_kernel(const float* __restrict__ y, const float* __restrict__ proj,
                     const float* __restrict__ nw, float* __restrict__ outn)
{
    const int b = blockIdx.x, s = b >> 3, g = b & 7;
    const int tid = threadIdx.x, lane = tid & 31, wid = tid >> 5;

    float4 yv = *reinterpret_cast<const float4*>(&y   [(size_t)s*I_DIM + g*1024 + tid*4]);
    float4 gv = *reinterpret_cast<const float4*>(&proj[(size_t)s*PROJ  + g*1024 + tid*4]);
    float4 t;
    t.x = yv.x * silu_f(gv.x); t.y = yv.y * silu_f(gv.y);
    t.z = yv.z * silu_f(gv.z); t.w = yv.w * silu_f(gv.w);

    float ss = t.x*t.x + t.y*t.y + t.z*t.z + t.w*t.w;
    #pragma unroll
    for (int o = 16; o; o >>= 1) ss += __shfl_xor_sync(0xffffffffu, ss, o);

    __shared__ float red[8];
    __shared__ float sscale;
    if (lane == 0) red[wid] = ss;
    __syncthreads();
    if (tid == 0) {
        float tot = 0.f;
        #pragma unroll
        for (int i = 0; i < 8; i++) tot += red[i];
        sscale = rsqrtf(tot * (1.0f/1024.0f) + 1e-5f);
    }
    __syncthreads();
    const float sc = sscale;

    float4 wv = *reinterpret_cast<const float4*>(&nw[g*1024 + tid*4]);
    float4 o;
    o.x = t.x*sc*wv.x; o.y = t.y*sc*wv.y; o.z = t.z*sc*wv.z; o.w = t.w*sc*wv.w;
    *reinterpret_cast<float4*>(&outn[(size_t)s*I_DIM + g*1024 + tid*4]) = o;
}

// ---------------- launcher ----------------
extern "C" void kernel_launch(void* const* d_in, const int* in_sizes, int n_in,
                              void* d_out, int out_size)
{
    const float* hidden     = (const float*)d_in[0];
    const float* conv_state = (const float*)d_in[1];
    const float* ssm_state  = (const float*)d_in[2];
    const float* W_in       = (const float*)d_in[3];
    const float* W_out      = (const float*)d_in[4];
    const float* conv_w     = (const float*)d_in[5];
    const float* conv_b     = (const float*)d_in[6];
    const float* A_log      = (const float*)d_in[7];
    const float* Dv         = (const float*)d_in[8];
    const float* dt_bias    = (const float*)d_in[9];
    const float* norm_w     = (const float*)d_in[10];

    float* out_main   = (float*)d_out;
    float* out_cstate = out_main + (size_t)S_LEN * HID;
    float* out_sstate = out_cstate + (size_t)CD * KCONV;

    float* proj = nullptr, *conv = nullptr, *yb = nullptr, *normed = nullptr;
    cudaGetSymbolAddress((void**)&proj,   g_proj);
    cudaGetSymbolAddress((void**)&conv,   g_conv);
    cudaGetSymbolAddress((void**)&yb,     g_y);
    cudaGetSymbolAddress((void**)&normed, g_normed);

    cudaFuncSetAttribute(gemm_tf32_nt, cudaFuncAttributeMaxDynamicSharedMemorySize, GEMM_SMEM);

    // 1. projected = hidden @ W_in^T : M=2048, N=18560, K=4096   (m fast axis)
    {
        dim3 grid(S_LEN / 128, PROJ / 128);
        gemm_tf32_nt<<<grid, 256, GEMM_SMEM>>>(hidden, W_in, proj, S_LEN, PROJ, HID);
    }
    // 2. conv + silu ; conv_state_out
    {
        dim3 grid(CD / 256, S_LEN / 128);
        conv_kernel<<<grid, 256>>>(proj, conv_state, conv_w, conv_b, conv);
        cstate_out_kernel<<<(CD * KCONV + 255) / 256, 256>>>(proj, out_cstate);
    }
    // 3. scan
    scan_kernel<<<H_HEADS, 256>>>(proj, conv, ssm_state, A_log, Dv, dt_bias, yb, out_sstate);
    // 4. gate + norm
    gatenorm_kernel<<<S_LEN * G_GRP, 256>>>(yb, proj, norm_w, normed);
    // 5. output = normed @ W_out^T : M=2048, N=4096, K=8192   (m fast axis)
    {
        dim3 grid(S_LEN / 128, HID / 128);
        gemm_tf32_nt<<<grid, 256, GEMM_SMEM>>>(normed, W_out, out_main, S_LEN, HID, I_DIM);
    }
}

// round 9
// speedup vs baseline: 1.4830x; 1.4830x over previous
#include <cuda_runtime.h>
#include <cuda_fp16.h>
#include <cstdint>

#define S_LEN   2048
#define HID     4096
#define I_DIM   8192
#define CD      10240
#define H_HEADS 128
#define P_DIM   64
#define G_GRP   8
#define N_STATE 128
#define KCONV   4
#define PROJ    18560   // I + CD + H

// device scratch
__device__ float  g_proj  [(size_t)S_LEN * PROJ ];
__device__ float  g_conv  [(size_t)S_LEN * CD   ];
__device__ float  g_y     [(size_t)S_LEN * I_DIM];
__device__ __half g_hid_h [(size_t)S_LEN * HID  ];
__device__ __half g_win_h [(size_t)PROJ  * HID  ];
__device__ __half g_wout_h[(size_t)HID   * I_DIM];
__device__ __half g_norm_h[(size_t)S_LEN * I_DIM];

__device__ __forceinline__ float silu_f(float v) { return v / (1.0f + expf(-v)); }

__device__ __forceinline__ void mma_f16(float* d, const uint32_t* a, const uint32_t* b) {
    asm volatile("mma.sync.aligned.m16n8k16.row.col.f32.f16.f16.f32 "
        "{%0,%1,%2,%3}, {%4,%5,%6,%7}, {%8,%9}, {%0,%1,%2,%3};\n"
        : "+f"(d[0]), "+f"(d[1]), "+f"(d[2]), "+f"(d[3])
        : "r"(a[0]), "r"(a[1]), "r"(a[2]), "r"(a[3]), "r"(b[0]), "r"(b[1]));
}
__device__ __forceinline__ void cp_async16(uint32_t smem_dst, const void* gmem_src) {
    asm volatile("cp.async.cg.shared.global [%0], [%1], 16;" :: "r"(smem_dst), "l"(gmem_src) : "memory");
}

// ---------------- GEMM (NT, fp16 in / fp32 out): C[M][Nn] = A * B^T ----------------
// Block 128x128x32, 8 warps (warp tile 64x32), 3-stage cp.async, 2 CTAs/SM.
// M,Nn multiples of 128; Kk multiple of 32 (true for all calls).
#define GSTG  3
#define KT    32            // halves per k-stage
#define RSH   40            // smem row stride in halves (80B)
#define TILEH (128 * RSH)   // halves per operand tile

__global__ __launch_bounds__(256, 2)
void gemm_f16_nt(const __half* __restrict__ A, const __half* __restrict__ B,
                 float* __restrict__ C, int M, int Nn, int Kk)
{
    extern __shared__ __half sm_[];
    __half* Asm = sm_;                  // [GSTG][TILEH]
    __half* Bsm = sm_ + GSTG * TILEH;   // [GSTG][TILEH]

    const int tid = threadIdx.x, lane = tid & 31, wid = tid >> 5;
    const int gid = lane >> 2, tig = lane & 3;
    const int wm = (wid >> 2) * 64, wn = (wid & 3) * 32;
    const int m0 = blockIdx.y * 128, n0 = blockIdx.x * 128;
    const int lr = tid >> 1;            // row 0..127
    const int lh = (tid & 1) * 16;      // half-offset 0 or 16 within the 32-half row

    float acc[4][4][4];
    #pragma unroll
    for (int i = 0; i < 4; i++)
        #pragma unroll
        for (int j = 0; j < 4; j++)
            #pragma unroll
            for (int r = 0; r < 4; r++) acc[i][j][r] = 0.f;

    const __half* Abase = &A[(size_t)(m0 + lr) * Kk + lh];
    const __half* Bbase = &B[(size_t)(n0 + lr) * Kk + lh];
    const uint32_t asm0 = (uint32_t)__cvta_generic_to_shared(Asm);
    const uint32_t bsm0 = (uint32_t)__cvta_generic_to_shared(Bsm);
    const uint32_t dsto = (uint32_t)(lr * RSH + lh) * 2;   // byte offset within a tile

    const int nk = Kk / KT;

    auto issue_stage = [&](int i) {
        if (i < nk) {
            const int k0 = i * KT, stg = i % GSTG;
            const uint32_t ad = asm0 + (uint32_t)stg * TILEH * 2 + dsto;
            const uint32_t bd = bsm0 + (uint32_t)stg * TILEH * 2 + dsto;
            cp_async16(ad,      Abase + k0);
            cp_async16(ad + 16, Abase + k0 + 8);
            cp_async16(bd,      Bbase + k0);
            cp_async16(bd + 16, Bbase + k0 + 8);
        }
        asm volatile("cp.async.commit_group;" ::: "memory");
    };

    issue_stage(0);
    issue_stage(1);

    for (int i = 0; i < nk; i++) {
        if (i + 1 < nk) asm volatile("cp.async.wait_group 1;" ::: "memory");
        else            asm volatile("cp.async.wait_group 0;" ::: "memory");
        __syncthreads();
        issue_stage(i + 2);

        const __half* as = Asm + (i % GSTG) * TILEH;
        const __half* bs = Bsm + (i % GSTG) * TILEH;

        #pragma unroll
        for (int ks = 0; ks < KT; ks += 16) {
            uint32_t af[4][4];
            #pragma unroll
            for (int mt = 0; mt < 4; mt++) {
                int r = wm + mt * 16 + gid;
                af[mt][0] = *(const uint32_t*)&as[ r      * RSH + ks + 2*tig    ];
                af[mt][1] = *(const uint32_t*)&as[(r + 8) * RSH + ks + 2*tig    ];
                af[mt][2] = *(const uint32_t*)&as[ r      * RSH + ks + 2*tig + 8];
                af[mt][3] = *(const uint32_t*)&as[(r + 8) * RSH + ks + 2*tig + 8];
            }
            uint32_t bf[4][2];
            #pragma unroll
            for (int nt = 0; nt < 4; nt++) {
                int cn = wn + nt * 8 + gid;
                bf[nt][0] = *(const uint32_t*)&bs[cn * RSH + ks + 2*tig    ];
                bf[nt][1] = *(const uint32_t*)&bs[cn * RSH + ks + 2*tig + 8];
            }
            #pragma unroll
            for (int mt = 0; mt < 4; mt++)
                #pragma unroll
                for (int nt = 0; nt < 4; nt++)
                    mma_f16(acc[mt][nt], af[mt], bf[nt]);
        }
        __syncthreads();
    }

    #pragma unroll
    for (int mt = 0; mt < 4; mt++) {
        int row = m0 + wm + mt * 16 + gid;
        #pragma unroll
        for (int nt = 0; nt < 4; nt++) {
            int col = n0 + wn + nt * 8 + 2 * tig;
            *reinterpret_cast<float2*>(&C[(size_t)row       * Nn + col]) = make_float2(acc[mt][nt][0], acc[mt][nt][1]);
            *reinterpret_cast<float2*>(&C[(size_t)(row + 8) * Nn + col]) = make_float2(acc[mt][nt][2], acc[mt][nt][3]);
        }
    }
}
#define GEMM_SMEM (GSTG * TILEH * 2 * (int)sizeof(__half))   // 61440 B

// ---------------- f32 -> f16 conversion ----------------
__global__ __launch_bounds__(256)
void cvt_f16_kernel(const float4* __restrict__ in, __half2* __restrict__ out, int n4)
{
    int i = blockIdx.x * 256 + threadIdx.x;
    int stride = gridDim.x * 256;
    for (; i < n4; i += stride) {
        float4 v = in[i];
        out[2*i]   = __floats2half2_rn(v.x, v.y);
        out[2*i+1] = __floats2half2_rn(v.z, v.w);
    }
}

// ---------------- conv1d K=4 + SiLU ----------------
__global__ __launch_bounds__(256)
void conv_kernel(const float* __restrict__ proj, const float* __restrict__ cstate,
                 const float* __restrict__ cw, const float* __restrict__ cb,
                 float* __restrict__ convout)
{
    const int c  = blockIdx.x * 256 + threadIdx.x;
    const int s0 = blockIdx.y * 128;
    const float w0 = cw[c*4+0], w1 = cw[c*4+1], w2 = cw[c*4+2], w3 = cw[c*4+3];
    const float bb = cb[c];
    auto xr = [&](int r) -> float {
        return (r < 0) ? cstate[c*4 + r + 4] : proj[(size_t)r*PROJ + I_DIM + c];
    };
    float x0 = xr(s0-3), x1 = xr(s0-2), x2 = xr(s0-1);
    #pragma unroll 4
    for (int s = s0; s < s0 + 128; s++) {
        float x3 = xr(s);
        float a  = bb + x0*w0 + x1*w1 + x2*w2 + x3*w3;
        convout[(size_t)s*CD + c] = silu_f(a);
        x0 = x1; x1 = x2; x2 = x3;
    }
}

__global__ void cstate_out_kernel(const float* __restrict__ proj, float* __restrict__ outc)
{
    int i = blockIdx.x * 256 + threadIdx.x;
    if (i < CD * KCONV) {
        int c = i >> 2, k = i & 3;
        outc[i] = proj[(size_t)(S_LEN - KCONV + k)*PROJ + I_DIM + c];
    }
}

// ---------------- sequential SSM scan: 1 block/head ----------------
__global__ __launch_bounds__(256, 1)
void scan_kernel(const float* __restrict__ proj, const float* __restrict__ conv,
                 const float* __restrict__ state_in,
                 const float* __restrict__ A_log, const float* __restrict__ Dv,
                 const float* __restrict__ dt_bias,
                 float* __restrict__ y_out, float* __restrict__ state_out)
{
    const int h = blockIdx.x, tid = threadIdx.x;
    const int p = tid >> 2, q = tid & 3;
    const int g = h >> 4;

    __shared__ __align__(16) float xs [3][64];
    __shared__ __align__(16) float Bsh[3][4*36];
    __shared__ __align__(16) float Csh[3][4*36];
    __shared__ float dts[3];

    const float Ah  = -expf(A_log[h]);
    const float Dh  = Dv[h];
    const float dtb = dt_bias[h];

    float st[32];
    { const float4* sp = reinterpret_cast<const float4*>(&state_in[((size_t)(h*64+p))*128 + q*32]);
      #pragma unroll
      for (int j = 0; j < 8; j++) {
          float4 v = sp[j];
          st[4*j+0]=v.x; st[4*j+1]=v.y; st[4*j+2]=v.z; st[4*j+3]=v.w;
      } }

    float rx = 0.f, rdt = 0.f;
    float4 rB = make_float4(0,0,0,0), rC = rB;

    auto issue_load = [&](int s) {
        const float* row = conv + (size_t)s * CD;
        if (tid < 64)        rx = row[h*64 + tid];
        else if (tid < 96)   rB = reinterpret_cast<const float4*>(row + I_DIM + g*128)[tid-64];
        else if (tid < 128)  rC = reinterpret_cast<const float4*>(row + I_DIM + G_GRP*N_STATE + g*128)[tid-96];
        else if (tid == 128) rdt = proj[(size_t)s*PROJ + I_DIM + CD + h];
    };
    auto store_smem = [&](int buf) {
        if (tid < 64)        xs[buf][tid] = rx;
        else if (tid < 96)  { int j = tid-64, qq = j>>3, jj = j&7;
                              *reinterpret_cast<float4*>(&Bsh[buf][qq*36 + jj*4]) = rB; }
        else if (tid < 128) { int j = tid-96, qq = j>>3, jj = j&7;
                              *reinterpret_cast<float4*>(&Csh[buf][qq*36 + jj*4]) = rC; }
        else if (tid == 128) dts[buf] = rdt;
    };

    issue_load(0);
    for (int s = 0; s < S_LEN; s++) {
        const int buf = s % 3;
        store_smem(buf);
        __syncthreads();
        if (s + 1 < S_LEN) issue_load(s + 1);

        const float dtr = dts[buf] + dtb;
        const float dt  = (dtr > 20.f) ? dtr : log1pf(expf(dtr));
        const float dA  = expf(dt * Ah);
        const float xv  = xs[buf][p];
        const float dx  = dt * xv;

        float accv = 0.f;
        const float4* bp = reinterpret_cast<const float4*>(&Bsh[buf][q*36]);
        const float4* cp = reinterpret_cast<const float4*>(&Csh[buf][q*36]);
        #pragma unroll
        for (int jj = 0; jj < 8; jj++) {
            float4 b4 = bp[jj], c4 = cp[jj];
            st[4*jj+0] = st[4*jj+0]*dA + dx*b4.x; accv += st[4*jj+0]*c4.x;
            st[4*jj+1] = st[4*jj+1]*dA + dx*b4.y; accv += st[4*jj+1]*c4.y;
            st[4*jj+2] = st[4*jj+2]*dA + dx*b4.z; accv += st[4*jj+2]*c4.z;
            st[4*jj+3] = st[4*jj+3]*dA + dx*b4.w; accv += st[4*jj+3]*c4.w;
        }
        accv += __shfl_xor_sync(0xffffffffu, accv, 1);
        accv += __shfl_xor_sync(0xffffffffu, accv, 2);
        if (q == 0) y_out[(size_t)s*I_DIM + h*64 + p] = accv + Dh*xv;
    }

    { float4* spo = reinterpret_cast<float4*>(&state_out[((size_t)(h*64+p))*128 + q*32]);
      #pragma unroll
      for (int j = 0; j < 8; j++)
          spo[j] = make_float4(st[4*j], st[4*j+1], st[4*j+2], st[4*j+3]); }
}

// ---------------- gate * silu + grouped RMSNorm -> fp16 ----------------
__global__ __launch_bounds__(256)
void gatenorm_kernel(const float* __restrict__ y, const float* __restrict__ proj,
                     const float* __restrict__ nw, __half* __restrict__ outn)
{
    const int b = blockIdx.x, s = b >> 3, g = b & 7;
    const int tid = threadIdx.x, lane = tid & 31, wid = tid >> 5;

    float4 yv = *reinterpret_cast<const float4*>(&y   [(size_t)s*I_DIM + g*1024 + tid*4]);
    float4 gv = *reinterpret_cast<const float4*>(&proj[(size_t)s*PROJ  + g*1024 + tid*4]);
    float4 t;
    t.x = yv.x * silu_f(gv.x); t.y = yv.y * silu_f(gv.y);
    t.z = yv.z * silu_f(gv.z); t.w = yv.w * silu_f(gv.w);

    float ss = t.x*t.x + t.y*t.y + t.z*t.z + t.w*t.w;
    #pragma unroll
    for (int o = 16; o; o >>= 1) ss += __shfl_xor_sync(0xffffffffu, ss, o);

    __shared__ float red[8];
    __shared__ float sscale;
    if (lane == 0) red[wid] = ss;
    __syncthreads();
    if (tid == 0) {
        float tot = 0.f;
        #pragma unroll
        for (int i = 0; i < 8; i++) tot += red[i];
        sscale = rsqrtf(tot * (1.0f/1024.0f) + 1e-5f);
    }
    __syncthreads();
    const float sc = sscale;

    float4 wv = *reinterpret_cast<const float4*>(&nw[g*1024 + tid*4]);
    __half2* op = reinterpret_cast<__half2*>(&outn[(size_t)s*I_DIM + g*1024 + tid*4]);
    op[0] = __floats2half2_rn(t.x*sc*wv.x, t.y*sc*wv.y);
    op[1] = __floats2half2_rn(t.z*sc*wv.z, t.w*sc*wv.w);
}

// ---------------- launcher ----------------
extern "C" void kernel_launch(void* const* d_in, const int* in_sizes, int n_in,
                              void* d_out, int out_size)
{
    const float* hidden     = (const float*)d_in[0];
    const float* conv_state = (const float*)d_in[1];
    const float* ssm_state  = (const float*)d_in[2];
    const float* W_in       = (const float*)d_in[3];
    const float* W_out      = (const float*)d_in[4];
    const float* conv_w     = (const float*)d_in[5];
    const float* conv_b     = (const float*)d_in[6];
    const float* A_log      = (const float*)d_in[7];
    const float* Dv         = (const float*)d_in[8];
    const float* dt_bias    = (const float*)d_in[9];
    const float* norm_w     = (const float*)d_in[10];

    float* out_main   = (float*)d_out;
    float* out_cstate = out_main + (size_t)S_LEN * HID;
    float* out_sstate = out_cstate + (size_t)CD * KCONV;

    float *proj, *conv, *yb;
    __half *hid_h, *win_h, *wout_h, *norm_h;
    cudaGetSymbolAddress((void**)&proj,   g_proj);
    cudaGetSymbolAddress((void**)&conv,   g_conv);
    cudaGetSymbolAddress((void**)&yb,     g_y);
    cudaGetSymbolAddress((void**)&hid_h,  g_hid_h);
    cudaGetSymbolAddress((void**)&win_h,  g_win_h);
    cudaGetSymbolAddress((void**)&wout_h, g_wout_h);
    cudaGetSymbolAddress((void**)&norm_h, g_norm_h);

    cudaFuncSetAttribute(gemm_f16_nt, cudaFuncAttributeMaxDynamicSharedMemorySize, GEMM_SMEM);

    // 0. convert GEMM operands to fp16
    cvt_f16_kernel<<<2048, 256>>>((const float4*)hidden, (__half2*)hid_h,  (int)((size_t)S_LEN*HID/4));
    cvt_f16_kernel<<<4096, 256>>>((const float4*)W_in,   (__half2*)win_h,  (int)((size_t)PROJ*HID/4));
    cvt_f16_kernel<<<4096, 256>>>((const float4*)W_out,  (__half2*)wout_h, (int)((size_t)HID*I_DIM/4));

    // 1. projected = hidden @ W_in^T : M=2048, N=18560, K=4096
    {
        dim3 grid(PROJ / 128, S_LEN / 128);
        gemm_f16_nt<<<grid, 256, GEMM_SMEM>>>(hid_h, win_h, proj, S_LEN, PROJ, HID);
    }
    // 2. conv + silu ; conv_state_out
    {
        dim3 grid(CD / 256, S_LEN / 128);
        conv_kernel<<<grid, 256>>>(proj, conv_state, conv_w, conv_b, conv);
        cstate_out_kernel<<<(CD * KCONV + 255) / 256, 256>>>(proj, out_cstate);
    }
    // 3. scan
    scan_kernel<<<H_HEADS, 256>>>(proj, conv, ssm_state, A_log, Dv, dt_bias, yb, out_sstate);
    // 4. gate + norm -> fp16
    gatenorm_kernel<<<S_LEN * G_GRP, 256>>>(yb, proj, norm_w, norm_h);
    // 5. output = normed @ W_out^T : M=2048, N=4096, K=8192
    {
        dim3 grid(HID / 128, S_LEN / 128);
        gemm_f16_nt<<<grid, 256, GEMM_SMEM>>>(norm_h, wout_h, out_main, S_LEN, HID, I_DIM);
    }
}

// round 10
// speedup vs baseline: 1.5520x; 1.0465x over previous
#include <cuda_runtime.h>
#include <cuda_fp16.h>
#include <cstdint>

#define S_LEN   2048
#define HID     4096
#define I_DIM   8192
#define CD      10240
#define H_HEADS 128
#define P_DIM   64
#define G_GRP   8
#define N_STATE 128
#define KCONV   4
#define PROJ    18560   // I + CD + H

// device scratch
__device__ float  g_proj  [(size_t)S_LEN * PROJ ];
__device__ float  g_conv  [(size_t)S_LEN * CD   ];
__device__ float  g_y     [(size_t)S_LEN * I_DIM];
__device__ __half g_hid_h [(size_t)S_LEN * HID  ];
__device__ __half g_win_h [(size_t)PROJ  * HID  ];
__device__ __half g_wout_h[(size_t)HID   * I_DIM];
__device__ __half g_norm_h[(size_t)S_LEN * I_DIM];

__device__ __forceinline__ float silu_f(float v) { return v / (1.0f + expf(-v)); }

__device__ __forceinline__ void mma_f16(float* d, const uint32_t* a, const uint32_t* b) {
    asm volatile("mma.sync.aligned.m16n8k16.row.col.f32.f16.f16.f32 "
        "{%0,%1,%2,%3}, {%4,%5,%6,%7}, {%8,%9}, {%0,%1,%2,%3};\n"
        : "+f"(d[0]), "+f"(d[1]), "+f"(d[2]), "+f"(d[3])
        : "r"(a[0]), "r"(a[1]), "r"(a[2]), "r"(a[3]), "r"(b[0]), "r"(b[1]));
}
__device__ __forceinline__ void cp_async16(uint32_t smem_dst, const void* gmem_src) {
    asm volatile("cp.async.cg.shared.global [%0], [%1], 16;" :: "r"(smem_dst), "l"(gmem_src) : "memory");
}
__device__ __forceinline__ void ldsm_x4(uint32_t& r0, uint32_t& r1, uint32_t& r2, uint32_t& r3, uint32_t a) {
    asm volatile("ldmatrix.sync.aligned.m8n8.x4.shared.b16 {%0,%1,%2,%3}, [%4];"
                 : "=r"(r0), "=r"(r1), "=r"(r2), "=r"(r3) : "r"(a));
}

// ---------------- GEMM (NT, fp16 in / fp32 out): C[M][Nn] = A * B^T ----------------
// Block 128x128x32, 8 warps (warp tile 64x32), 3-stage cp.async, 2 CTAs/SM,
// ldmatrix.x4 fragment loads, single barrier per k-iter.
#define GSTG  3
#define KT    32            // halves per k-stage
#define RSH   40            // smem row stride in halves (80B) — conflict-free for LDSM
#define TILEH (128 * RSH)

__global__ __launch_bounds__(256, 2)
void gemm_f16_nt(const __half* __restrict__ A, const __half* __restrict__ B,
                 float* __restrict__ C, int M, int Nn, int Kk)
{
    extern __shared__ __half sm_[];
    __half* Asm = sm_;
    __half* Bsm = sm_ + GSTG * TILEH;

    const int tid = threadIdx.x, lane = tid & 31, wid = tid >> 5;
    const int gid = lane >> 2, tig = lane & 3;
    const int wm = (wid >> 2) * 64, wn = (wid & 3) * 32;
    const int m0 = blockIdx.y * 128, n0 = blockIdx.x * 128;
    const int lr = tid >> 1;
    const int lh = (tid & 1) * 16;

    float acc[4][4][4];
    #pragma unroll
    for (int i = 0; i < 4; i++)
        #pragma unroll
        for (int j = 0; j < 4; j++)
            #pragma unroll
            for (int r = 0; r < 4; r++) acc[i][j][r] = 0.f;

    const __half* Abase = &A[(size_t)(m0 + lr) * Kk + lh];
    const __half* Bbase = &B[(size_t)(n0 + lr) * Kk + lh];
    const uint32_t asm0 = (uint32_t)__cvta_generic_to_shared(Asm);
    const uint32_t bsm0 = (uint32_t)__cvta_generic_to_shared(Bsm);
    const uint32_t dsto = (uint32_t)(lr * RSH + lh) * 2;
    // ldmatrix per-lane offset: row = lane&15, k-offset = 8*(lane>>4)
    const uint32_t lanoff = (uint32_t)(((lane & 15) * RSH + 8 * (lane >> 4)) * 2);

    const int nk = Kk / KT;

    auto issue_stage = [&](int i) {
        if (i < nk) {
            const int k0 = i * KT, stg = i % GSTG;
            const uint32_t ad = asm0 + (uint32_t)stg * TILEH * 2 + dsto;
            const uint32_t bd = bsm0 + (uint32_t)stg * TILEH * 2 + dsto;
            cp_async16(ad,      Abase + k0);
            cp_async16(ad + 16, Abase + k0 + 8);
            cp_async16(bd,      Bbase + k0);
            cp_async16(bd + 16, Bbase + k0 + 8);
        }
        asm volatile("cp.async.commit_group;" ::: "memory");
    };

    issue_stage(0);
    issue_stage(1);

    for (int i = 0; i < nk; i++) {
        if (i + 1 < nk) asm volatile("cp.async.wait_group 1;" ::: "memory");
        else            asm volatile("cp.async.wait_group 0;" ::: "memory");
        __syncthreads();
        issue_stage(i + 2);   // writes buffer (i+2)%3; its readers finished before this barrier

        const uint32_t abase = asm0 + (uint32_t)(i % GSTG) * TILEH * 2 + lanoff;
        const uint32_t bbase = bsm0 + (uint32_t)(i % GSTG) * TILEH * 2 + lanoff;

        #pragma unroll
        for (int ks = 0; ks < KT; ks += 16) {
            uint32_t af[4][4];
            #pragma unroll
            for (int mt = 0; mt < 4; mt++)
                ldsm_x4(af[mt][0], af[mt][1], af[mt][2], af[mt][3],
                        abase + (uint32_t)(((wm + mt * 16) * RSH + ks) * 2));
            uint32_t bf[4][2];
            #pragma unroll
            for (int pr = 0; pr < 2; pr++) {
                uint32_t r0, r1, r2, r3;
                ldsm_x4(r0, r1, r2, r3,
                        bbase + (uint32_t)(((wn + pr * 16) * RSH + ks) * 2));
                bf[2*pr][0] = r0; bf[2*pr+1][0] = r1;
                bf[2*pr][1] = r2; bf[2*pr+1][1] = r3;
            }
            #pragma unroll
            for (int mt = 0; mt < 4; mt++)
                #pragma unroll
                for (int nt = 0; nt < 4; nt++)
                    mma_f16(acc[mt][nt], af[mt], bf[nt]);
        }
        // no trailing barrier: next iteration's barrier orders buffer reuse
    }

    #pragma unroll
    for (int mt = 0; mt < 4; mt++) {
        int row = m0 + wm + mt * 16 + gid;
        #pragma unroll
        for (int nt = 0; nt < 4; nt++) {
            int col = n0 + wn + nt * 8 + 2 * tig;
            *reinterpret_cast<float2*>(&C[(size_t)row       * Nn + col]) = make_float2(acc[mt][nt][0], acc[mt][nt][1]);
            *reinterpret_cast<float2*>(&C[(size_t)(row + 8) * Nn + col]) = make_float2(acc[mt][nt][2], acc[mt][nt][3]);
        }
    }
}
#define GEMM_SMEM (GSTG * TILEH * 2 * (int)sizeof(__half))   // 61440 B

// ---------------- f32 -> f16 conversion ----------------
__global__ __launch_bounds__(256)
void cvt_f16_kernel(const float4* __restrict__ in, __half2* __restrict__ out, int n4)
{
    int i = blockIdx.x * 256 + threadIdx.x;
    int stride = gridDim.x * 256;
    for (; i < n4; i += stride) {
        float4 v = in[i];
        out[2*i]   = __floats2half2_rn(v.x, v.y);
        out[2*i+1] = __floats2half2_rn(v.z, v.w);
    }
}

// ---------------- conv1d K=4 + SiLU ----------------
__global__ __launch_bounds__(256)
void conv_kernel(const float* __restrict__ proj, const float* __restrict__ cstate,
                 const float* __restrict__ cw, const float* __restrict__ cb,
                 float* __restrict__ convout)
{
    const int c  = blockIdx.x * 256 + threadIdx.x;
    const int s0 = blockIdx.y * 128;
    const float w0 = cw[c*4+0], w1 = cw[c*4+1], w2 = cw[c*4+2], w3 = cw[c*4+3];
    const float bb = cb[c];
    auto xr = [&](int r) -> float {
        return (r < 0) ? cstate[c*4 + r + 4] : proj[(size_t)r*PROJ + I_DIM + c];
    };
    float x0 = xr(s0-3), x1 = xr(s0-2), x2 = xr(s0-1);
    #pragma unroll 4
    for (int s = s0; s < s0 + 128; s++) {
        float x3 = xr(s);
        float a  = bb + x0*w0 + x1*w1 + x2*w2 + x3*w3;
        convout[(size_t)s*CD + c] = silu_f(a);
        x0 = x1; x1 = x2; x2 = x3;
    }
}

__global__ void cstate_out_kernel(const float* __restrict__ proj, float* __restrict__ outc)
{
    int i = blockIdx.x * 256 + threadIdx.x;
    if (i < CD * KCONV) {
        int c = i >> 2, k = i & 3;
        outc[i] = proj[(size_t)(S_LEN - KCONV + k)*PROJ + I_DIM + c];
    }
}

// ---------------- sequential SSM scan: 1 block/head ----------------
__global__ __launch_bounds__(256, 1)
void scan_kernel(const float* __restrict__ proj, const float* __restrict__ conv,
                 const float* __restrict__ state_in,
                 const float* __restrict__ A_log, const float* __restrict__ Dv,
                 const float* __restrict__ dt_bias,
                 float* __restrict__ y_out, float* __restrict__ state_out)
{
    const int h = blockIdx.x, tid = threadIdx.x;
    const int p = tid >> 2, q = tid & 3;
    const int g = h >> 4;

    __shared__ __align__(16) float xs [3][64];
    __shared__ __align__(16) float Bsh[3][4*36];
    __shared__ __align__(16) float Csh[3][4*36];
    __shared__ float dts[3];

    const float Ah  = -expf(A_log[h]);
    const float Dh  = Dv[h];
    const float dtb = dt_bias[h];

    float st[32];
    { const float4* sp = reinterpret_cast<const float4*>(&state_in[((size_t)(h*64+p))*128 + q*32]);
      #pragma unroll
      for (int j = 0; j < 8; j++) {
          float4 v = sp[j];
          st[4*j+0]=v.x; st[4*j+1]=v.y; st[4*j+2]=v.z; st[4*j+3]=v.w;
      } }

    float rx = 0.f, rdt = 0.f;
    float4 rB = make_float4(0,0,0,0), rC = rB;

    auto issue_load = [&](int s) {
        const float* row = conv + (size_t)s * CD;
        if (tid < 64)        rx = row[h*64 + tid];
        else if (tid < 96)   rB = reinterpret_cast<const float4*>(row + I_DIM + g*128)[tid-64];
        else if (tid < 128)  rC = reinterpret_cast<const float4*>(row + I_DIM + G_GRP*N_STATE + g*128)[tid-96];
        else if (tid == 128) rdt = proj[(size_t)s*PROJ + I_DIM + CD + h];
    };
    auto store_smem = [&](int buf) {
        if (tid < 64)        xs[buf][tid] = rx;
        else if (tid < 96)  { int j = tid-64, qq = j>>3, jj = j&7;
                              *reinterpret_cast<float4*>(&Bsh[buf][qq*36 + jj*4]) = rB; }
        else if (tid < 128) { int j = tid-96, qq = j>>3, jj = j&7;
                              *reinterpret_cast<float4*>(&Csh[buf][qq*36 + jj*4]) = rC; }
        else if (tid == 128) dts[buf] = rdt;
    };

    issue_load(0);
    for (int s = 0; s < S_LEN; s++) {
        const int buf = s % 3;
        store_smem(buf);
        __syncthreads();
        if (s + 1 < S_LEN) issue_load(s + 1);

        const float dtr = dts[buf] + dtb;
        const float dt  = (dtr > 20.f) ? dtr : log1pf(expf(dtr));
        const float dA  = expf(dt * Ah);
        const float xv  = xs[buf][p];
        const float dx  = dt * xv;

        float accv = 0.f;
        const float4* bp = reinterpret_cast<const float4*>(&Bsh[buf][q*36]);
        const float4* cp = reinterpret_cast<const float4*>(&Csh[buf][q*36]);
        #pragma unroll
        for (int jj = 0; jj < 8; jj++) {
            float4 b4 = bp[jj], c4 = cp[jj];
            st[4*jj+0] = st[4*jj+0]*dA + dx*b4.x; accv += st[4*jj+0]*c4.x;
            st[4*jj+1] = st[4*jj+1]*dA + dx*b4.y; accv += st[4*jj+1]*c4.y;
            st[4*jj+2] = st[4*jj+2]*dA + dx*b4.z; accv += st[4*jj+2]*c4.z;
            st[4*jj+3] = st[4*jj+3]*dA + dx*b4.w; accv += st[4*jj+3]*c4.w;
        }
        accv += __shfl_xor_sync(0xffffffffu, accv, 1);
        accv += __shfl_xor_sync(0xffffffffu, accv, 2);
        if (q == 0) y_out[(size_t)s*I_DIM + h*64 + p] = accv + Dh*xv;
    }

    { float4* spo = reinterpret_cast<float4*>(&state_out[((size_t)(h*64+p))*128 + q*32]);
      #pragma unroll
      for (int j = 0; j < 8; j++)
          spo[j] = make_float4(st[4*j], st[4*j+1], st[4*j+2], st[4*j+3]); }
}

// ---------------- gate * silu + grouped RMSNorm -> fp16 ----------------
__global__ __launch_bounds__(256)
void gatenorm_kernel(const float* __restrict__ y, const float* __restrict__ proj,
                     const float* __restrict__ nw, __half* __restrict__ outn)
{
    const int b = blockIdx.x, s = b >> 3, g = b & 7;
    const int tid = threadIdx.x, lane = tid & 31, wid = tid >> 5;

    float4 yv = *reinterpret_cast<const float4*>(&y   [(size_t)s*I_DIM + g*1024 + tid*4]);
    float4 gv = *reinterpret_cast<const float4*>(&proj[(size_t)s*PROJ  + g*1024 + tid*4]);
    float4 t;
    t.x = yv.x * silu_f(gv.x); t.y = yv.y * silu_f(gv.y);
    t.z = yv.z * silu_f(gv.z); t.w = yv.w * silu_f(gv.w);

    float ss = t.x*t.x + t.y*t.y + t.z*t.z + t.w*t.w;
    #pragma unroll
    for (int o = 16; o; o >>= 1) ss += __shfl_xor_sync(0xffffffffu, ss, o);

    __shared__ float red[8];
    __shared__ float sscale;
    if (lane == 0) red[wid] = ss;
    __syncthreads();
    if (tid == 0) {
        float tot = 0.f;
        #pragma unroll
        for (int i = 0; i < 8; i++) tot += red[i];
        sscale = rsqrtf(tot * (1.0f/1024.0f) + 1e-5f);
    }
    __syncthreads();
    const float sc = sscale;

    float4 wv = *reinterpret_cast<const float4*>(&nw[g*1024 + tid*4]);
    __half2* op = reinterpret_cast<__half2*>(&outn[(size_t)s*I_DIM + g*1024 + tid*4]);
    op[0] = __floats2half2_rn(t.x*sc*wv.x, t.y*sc*wv.y);
    op[1] = __floats2half2_rn(t.z*sc*wv.z, t.w*sc*wv.w);
}

// ---------------- launcher ----------------
extern "C" void kernel_launch(void* const* d_in, const int* in_sizes, int n_in,
                              void* d_out, int out_size)
{
    const float* hidden     = (const float*)d_in[0];
    const float* conv_state = (const float*)d_in[1];
    const float* ssm_state  = (const float*)d_in[2];
    const float* W_in       = (const float*)d_in[3];
    const float* W_out      = (const float*)d_in[4];
    const float* conv_w     = (const float*)d_in[5];
    const float* conv_b     = (const float*)d_in[6];
    const float* A_log      = (const float*)d_in[7];
    const float* Dv         = (const float*)d_in[8];
    const float* dt_bias    = (const float*)d_in[9];
    const float* norm_w     = (const float*)d_in[10];

    float* out_main   = (float*)d_out;
    float* out_cstate = out_main + (size_t)S_LEN * HID;
    float* out_sstate = out_cstate + (size_t)CD * KCONV;

    float *proj, *conv, *yb;
    __half *hid_h, *win_h, *wout_h, *norm_h;
    cudaGetSymbolAddress((void**)&proj,   g_proj);
    cudaGetSymbolAddress((void**)&conv,   g_conv);
    cudaGetSymbolAddress((void**)&yb,     g_y);
    cudaGetSymbolAddress((void**)&hid_h,  g_hid_h);
    cudaGetSymbolAddress((void**)&win_h,  g_win_h);
    cudaGetSymbolAddress((void**)&wout_h, g_wout_h);
    cudaGetSymbolAddress((void**)&norm_h, g_norm_h);

    cudaFuncSetAttribute(gemm_f16_nt, cudaFuncAttributeMaxDynamicSharedMemorySize, GEMM_SMEM);

    // 0. convert GEMM operands to fp16
    cvt_f16_kernel<<<2048, 256>>>((const float4*)hidden, (__half2*)hid_h,  (int)((size_t)S_LEN*HID/4));
    cvt_f16_kernel<<<4096, 256>>>((const float4*)W_in,   (__half2*)win_h,  (int)((size_t)PROJ*HID/4));
    cvt_f16_kernel<<<4096, 256>>>((const float4*)W_out,  (__half2*)wout_h, (int)((size_t)HID*I_DIM/4));

    // 1. projected = hidden @ W_in^T : M=2048, N=18560, K=4096
    {
        dim3 grid(PROJ / 128, S_LEN / 128);
        gemm_f16_nt<<<grid, 256, GEMM_SMEM>>>(hid_h, win_h, proj, S_LEN, PROJ, HID);
    }
    // 2. conv + silu ; conv_state_out
    {
        dim3 grid(CD / 256, S_LEN / 128);
        conv_kernel<<<grid, 256>>>(proj, conv_state, conv_w, conv_b, conv);
        cstate_out_kernel<<<(CD * KCONV + 255) / 256, 256>>>(proj, out_cstate);
    }
    // 3. scan
    scan_kernel<<<H_HEADS, 256>>>(proj, conv, ssm_state, A_log, Dv, dt_bias, yb, out_sstate);
    // 4. gate + norm -> fp16
    gatenorm_kernel<<<S_LEN * G_GRP, 256>>>(yb, proj, norm_w, norm_h);
    // 5. output = normed @ W_out^T : M=2048, N=4096, K=8192
    {
        dim3 grid(HID / 128, S_LEN / 128);
        gemm_f16_nt<<<grid, 256, GEMM_SMEM>>>(norm_h, wout_h, out_main, S_LEN, HID, I_DIM);
    }
}